// round 9
// baseline (speedup 1.0000x reference)
#include <cuda_runtime.h>
#include <cstdint>

#define B_ROWS 8192
#define N_NODES 2048
#define DIM 128
#define NSTRIPS 32
#define STRIP 64

// ---------------- scratch (static device memory only) ----------------
__device__ float g_ps[B_ROWS];
__device__ float g_ns[N_NODES];
__device__ __align__(16) float g_ns_sorted[N_NODES];
__device__ int   g_idx_sorted[N_NODES];
__device__ float g_nsmax;
__device__ float g_wpos[N_NODES];
__device__ float g_wneg[N_NODES];
__device__ __align__(16) float g_posw_n[N_NODES][DIM];   // exp(ns-D) * node row (sorted order)
__device__ __align__(16) float g_negw_n[N_NODES][DIM];   // exp(0.2(ns-D)) * node row
__device__ float g_stripPos[NSTRIPS][DIM];
__device__ float g_stripNeg[NSTRIPS][DIM];
__device__ float g_stripPosW[NSTRIPS];
__device__ float g_stripNegW[NSTRIPS];
__device__ float g_tailPos[NSTRIPS][DIM];   // sum of strips AFTER b (suffix offset)
__device__ float g_headNeg[NSTRIPS][DIM];   // sum of strips BEFORE b (prefix offset)
__device__ float g_tailPosW[NSTRIPS];
__device__ float g_headNegW[NSTRIPS];
__device__ __align__(16) float g_S[N_NODES + 1][DIM];    // S[c] = sum_{r>=c} posw_n[r]
__device__ __align__(16) float g_P[N_NODES + 1][DIM];    // P[c] = sum_{r<c}  negw_n[r]
__device__ float g_wS[N_NODES + 1];
__device__ float g_wP[N_NODES + 1];

// ---------------------------------------------------------------------------
// K1: row scores. 2 threads per row (patients then nodes), shfl-combined.
// ---------------------------------------------------------------------------
__global__ __launch_bounds__(256) void score_kernel(const float* __restrict__ pf,
                                                    const float* __restrict__ dn,
                                                    const float* __restrict__ ak) {
    int t = blockIdx.x * 256 + threadIdx.x;
    int row = t >> 1, h = t & 1;
    const float4* src;
    const float4* a;
    if (row < B_ROWS) {
        src = (const float4*)(pf + (size_t)row * DIM) + h * 16;
        a   = (const float4*)ak + h * 16;
    } else {
        int j = row - B_ROWS;
        src = (const float4*)(dn + (size_t)j * DIM) + h * 16;
        a   = (const float4*)(ak + DIM) + h * 16;
    }
    float s = 0.f;
    #pragma unroll
    for (int i = 0; i < 16; i++) {
        float4 x = src[i], y = a[i];
        s += x.x * y.x + x.y * y.y + x.z * y.z + x.w * y.w;
    }
    s += __shfl_xor_sync(0xffffffffu, s, 1);
    if (h == 0) {
        if (row < B_ROWS) g_ps[row] = s;
        else              g_ns[row - B_ROWS] = s;
    }
}

// ---------------------------------------------------------------------------
// K2: counting-sort ranks (2048^2 comparisons, 16 blocks x 128 nodes),
// scatter into sorted arrays; rank 2047 publishes the max.
// ---------------------------------------------------------------------------
__global__ __launch_bounds__(256) void rank_kernel() {
    __shared__ __align__(16) float ns_sm[N_NODES];
    int tid = threadIdx.x;
    for (int i = tid; i < N_NODES; i += 256) ns_sm[i] = g_ns[i];
    __syncthreads();

    int node = blockIdx.x * 128 + (tid >> 1);
    int half = tid & 1;
    float v = ns_sm[node];
    int cnt = 0;
    const float4* p4 = (const float4*)ns_sm + half * 256;
    #pragma unroll 8
    for (int i = 0; i < 256; i++) {
        float4 w = p4[i];
        int k = (half * 256 + i) * 4;
        cnt += (w.x < v) || (w.x == v && (k + 0) < node);
        cnt += (w.y < v) || (w.y == v && (k + 1) < node);
        cnt += (w.z < v) || (w.z == v && (k + 2) < node);
        cnt += (w.w < v) || (w.w == v && (k + 3) < node);
    }
    cnt += __shfl_xor_sync(0xffffffffu, cnt, 1);
    if (half == 0) {
        g_ns_sorted[cnt] = v;
        g_idx_sorted[cnt] = node;
        if (cnt == N_NODES - 1) g_nsmax = v;
    }
}

// ---------------------------------------------------------------------------
// K3: per-strip (64 sorted rows): weights, permuted weighted node rows,
// and per-strip partial sums (vector + scalar).
// ---------------------------------------------------------------------------
__global__ __launch_bounds__(256) void permute_kernel(const float* __restrict__ dn) {
    __shared__ float wps[STRIP], wns[STRIP];
    __shared__ int idx_sm[STRIP];
    __shared__ float part[2][2][DIM];
    int b = blockIdx.x, tid = threadIdx.x;
    int r0 = b * STRIP;

    if (tid < STRIP) {
        float D = g_nsmax;
        float nsv = g_ns_sorted[r0 + tid];
        float wp = expf(nsv - D);
        float wn = expf(0.2f * (nsv - D));
        wps[tid] = wp; wns[tid] = wn;
        idx_sm[tid] = g_idx_sorted[r0 + tid];
        g_wpos[r0 + tid] = wp;
        g_wneg[r0 + tid] = wn;
    }
    __syncthreads();

    int d = tid & 127, h = tid >> 7;
    float accp = 0.f, accn = 0.f;
    for (int rr = h * 32; rr < h * 32 + 32; rr++) {
        float n = dn[(size_t)idx_sm[rr] * DIM + d];
        float p = wps[rr] * n, qv = wns[rr] * n;
        g_posw_n[r0 + rr][d] = p;
        g_negw_n[r0 + rr][d] = qv;
        accp += p; accn += qv;
    }
    part[h][0][d] = accp;
    part[h][1][d] = accn;
    __syncthreads();
    if (h == 0) {
        g_stripPos[b][d] = part[0][0][d] + part[1][0][d];
        g_stripNeg[b][d] = part[0][1][d] + part[1][1][d];
    } else if (d < 2) {
        float s = 0.f;
        if (d == 0) { for (int r = 0; r < STRIP; r++) s += wps[r]; g_stripPosW[b] = s; }
        else        { for (int r = 0; r < STRIP; r++) s += wns[r]; g_stripNegW[b] = s; }
    }
}

// ---------------------------------------------------------------------------
// K4: scan of the 32 strip sums (per dim + scalars). One small block.
// ---------------------------------------------------------------------------
__global__ __launch_bounds__(160) void stripscan_kernel() {
    int t = threadIdx.x;
    if (t < DIM) {
        float acc = 0.f;
        for (int b = NSTRIPS - 1; b >= 0; b--) { g_tailPos[b][t] = acc; acc += g_stripPos[b][t]; }
        float acc2 = 0.f;
        for (int b = 0; b < NSTRIPS; b++) { g_headNeg[b][t] = acc2; acc2 += g_stripNeg[b][t]; }
    } else if (t == DIM) {
        float acc = 0.f;
        for (int b = NSTRIPS - 1; b >= 0; b--) { g_tailPosW[b] = acc; acc += g_stripPosW[b]; }
    } else if (t == DIM + 1) {
        float acc = 0.f;
        for (int b = 0; b < NSTRIPS; b++) { g_headNegW[b] = acc; acc += g_stripNegW[b]; }
    }
}

// ---------------------------------------------------------------------------
// K5: write full suffix/prefix tables (vector + scalar), 32 blocks (strips).
// ---------------------------------------------------------------------------
__global__ __launch_bounds__(288) void table_kernel() {
    int b = blockIdx.x, t = threadIdx.x, r0 = b * STRIP;
    if (t < DIM) {
        float acc = g_tailPos[b][t];
        for (int r = STRIP - 1; r >= 0; r--) { acc += g_posw_n[r0 + r][t]; g_S[r0 + r][t] = acc; }
        if (b == 0) g_S[N_NODES][t] = 0.f;
    } else if (t < 2 * DIM) {
        int d = t - DIM;
        float acc = g_headNeg[b][d];
        for (int r = 0; r < STRIP; r++) { acc += g_negw_n[r0 + r][d]; g_P[r0 + r + 1][d] = acc; }
        if (b == 0) g_P[0][d] = 0.f;
    } else if (t == 2 * DIM) {
        float acc = g_tailPosW[b];
        for (int r = STRIP - 1; r >= 0; r--) { acc += g_wpos[r0 + r]; g_wS[r0 + r] = acc; }
        if (b == 0) g_wS[N_NODES] = 0.f;
    } else if (t == 2 * DIM + 1) {
        float acc = g_headNegW[b];
        for (int r = 0; r < STRIP; r++) { acc += g_wneg[r0 + r]; g_wP[r0 + r + 1] = acc; }
        if (b == 0) g_wP[0] = 0.f;
    }
}

// ---------------------------------------------------------------------------
// K6: output. Per row: binary search crossover c, then
// out = pf + (A*S[c] + B*P[c]) / (A*wS[c] + B*wP[c]).
// A = exp(ps+D-m), B = exp(0.2(ps+D)-m), m = lrelu(ps+D). Both <= 1.
// ---------------------------------------------------------------------------
__global__ __launch_bounds__(256) void out_kernel(const float* __restrict__ pf,
                                                  float* __restrict__ out) {
    __shared__ __align__(16) float ns_sm[N_NODES];
    int tid = threadIdx.x;
    for (int i = tid; i < N_NODES; i += 256) ns_sm[i] = g_ns_sorted[i];
    __syncthreads();

    int row = blockIdx.x * 64 + (tid >> 2);
    int q = tid & 3;
    float ps = g_ps[row];
    float x = ps + g_nsmax;
    float m = fmaxf(x, 0.2f * x);
    float A = expf(x - m);
    float B = expf(0.2f * x - m);

    // c = count of sorted nodes with ns <= -ps  (suffix from c is the positive branch)
    float thr = -ps;
    int lo = 0, hi = N_NODES;
    while (lo < hi) {
        int mid = (lo + hi) >> 1;
        if (ns_sm[mid] <= thr) lo = mid + 1; else hi = mid;
    }
    int c = lo;

    float den = A * g_wS[c] + B * g_wP[c];
    float inv = 1.0f / den;

    const float4* pfp = (const float4*)(pf + (size_t)row * DIM) + q * 8;
    const float4* Sp  = (const float4*)g_S[c] + q * 8;
    const float4* Pp  = (const float4*)g_P[c] + q * 8;
    float4* op = (float4*)(out + (size_t)row * DIM) + q * 8;
    #pragma unroll
    for (int i = 0; i < 8; i++) {
        float4 p = pfp[i], sv = Sp[i], pv = Pp[i];
        float4 o;
        o.x = fmaf(fmaf(A, sv.x, B * pv.x), inv, p.x);
        o.y = fmaf(fmaf(A, sv.y, B * pv.y), inv, p.y);
        o.z = fmaf(fmaf(A, sv.z, B * pv.z), inv, p.z);
        o.w = fmaf(fmaf(A, sv.w, B * pv.w), inv, p.w);
        op[i] = o;
    }
}

// ---------------------------------------------------------------------------
extern "C" void kernel_launch(void* const* d_in, const int* in_sizes, int n_in,
                              void* d_out, int out_size) {
    const float* pf = (const float*)d_in[0];   // patient_features [8192,128]
    const float* dn = (const float*)d_in[1];   // disease_nodes   [2048,128]
    const float* ak = (const float*)d_in[2];   // attn_kernel     [256,1]
    float* out = (float*)d_out;

    score_kernel<<<(B_ROWS + N_NODES) * 2 / 256, 256>>>(pf, dn, ak);
    rank_kernel<<<N_NODES / 128, 256>>>();
    permute_kernel<<<NSTRIPS, 256>>>(dn);
    stripscan_kernel<<<1, 160>>>();
    table_kernel<<<NSTRIPS, 288>>>();
    out_kernel<<<B_ROWS / 64, 256>>>(pf, out);
}

// round 10
// speedup vs baseline: 1.2519x; 1.2519x over previous
#include <cuda_runtime.h>
#include <cstdint>

#define B_ROWS 8192
#define N_NODES 2048
#define DIM 128
#define NSTRIPS 32
#define STRIP 64

// ---------------- scratch (static device memory only) ----------------
__device__ float g_ps[B_ROWS];
__device__ float g_ns[N_NODES];
__device__ __align__(16) float g_ns_sorted[N_NODES];
__device__ int   g_idx_sorted[N_NODES];
__device__ float g_nsmax;
__device__ float g_wpos[N_NODES];
__device__ float g_wneg[N_NODES];
__device__ __align__(16) float g_posw_n[N_NODES][DIM];   // exp(ns-D) * node row (sorted order)
__device__ __align__(16) float g_negw_n[N_NODES][DIM];   // exp(0.2(ns-D)) * node row
__device__ float g_stripPos[NSTRIPS][DIM];
__device__ float g_stripNeg[NSTRIPS][DIM];
__device__ float g_stripPosW[NSTRIPS];
__device__ float g_stripNegW[NSTRIPS];
__device__ __align__(16) float g_S[N_NODES + 1][DIM];    // S[c] = sum_{r>=c} posw_n[r]
__device__ __align__(16) float g_P[N_NODES + 1][DIM];    // P[c] = sum_{r<c}  negw_n[r]
__device__ float g_wS[N_NODES + 1];
__device__ float g_wP[N_NODES + 1];

// ---------------------------------------------------------------------------
// K1: row scores. 4 threads per row (patients then nodes), shfl-combined.
// ---------------------------------------------------------------------------
__global__ __launch_bounds__(256) void score_kernel(const float* __restrict__ pf,
                                                    const float* __restrict__ dn,
                                                    const float* __restrict__ ak) {
    int t = blockIdx.x * 256 + threadIdx.x;
    int row = t >> 2, h = t & 3;
    const float4* src;
    const float4* a;
    if (row < B_ROWS) {
        src = (const float4*)(pf + (size_t)row * DIM) + h * 8;
        a   = (const float4*)ak + h * 8;
    } else {
        int j = row - B_ROWS;
        src = (const float4*)(dn + (size_t)j * DIM) + h * 8;
        a   = (const float4*)(ak + DIM) + h * 8;
    }
    float s = 0.f;
    #pragma unroll
    for (int i = 0; i < 8; i++) {
        float4 x = src[i], y = a[i];
        s += x.x * y.x + x.y * y.y + x.z * y.z + x.w * y.w;
    }
    s += __shfl_xor_sync(0xffffffffu, s, 1);
    s += __shfl_xor_sync(0xffffffffu, s, 2);
    if (h == 0) {
        if (row < B_ROWS) g_ps[row] = s;
        else              g_ns[row - B_ROWS] = s;
    }
}

// ---------------------------------------------------------------------------
// K2: counting-sort ranks (2048^2 comparisons, 16 blocks x 128 nodes),
// scatter into sorted arrays; rank 2047 publishes the max.
// ---------------------------------------------------------------------------
__global__ __launch_bounds__(256) void rank_kernel() {
    __shared__ __align__(16) float ns_sm[N_NODES];
    int tid = threadIdx.x;
    for (int i = tid; i < N_NODES; i += 256) ns_sm[i] = g_ns[i];
    __syncthreads();

    int node = blockIdx.x * 128 + (tid >> 1);
    int half = tid & 1;
    float v = ns_sm[node];
    int cnt = 0;
    const float4* p4 = (const float4*)ns_sm + half * 256;
    #pragma unroll 8
    for (int i = 0; i < 256; i++) {
        float4 w = p4[i];
        int k = (half * 256 + i) * 4;
        cnt += (w.x < v) || (w.x == v && (k + 0) < node);
        cnt += (w.y < v) || (w.y == v && (k + 1) < node);
        cnt += (w.z < v) || (w.z == v && (k + 2) < node);
        cnt += (w.w < v) || (w.w == v && (k + 3) < node);
    }
    cnt += __shfl_xor_sync(0xffffffffu, cnt, 1);
    if (half == 0) {
        g_ns_sorted[cnt] = v;
        g_idx_sorted[cnt] = node;
        if (cnt == N_NODES - 1) g_nsmax = v;
    }
}

// ---------------------------------------------------------------------------
// K3: per-strip (64 sorted rows): weights, permuted weighted node rows,
// and per-strip partial sums (vector + scalar).
// ---------------------------------------------------------------------------
__global__ __launch_bounds__(256) void permute_kernel(const float* __restrict__ dn) {
    __shared__ float wps[STRIP], wns[STRIP];
    __shared__ int idx_sm[STRIP];
    __shared__ float part[2][2][DIM];
    int b = blockIdx.x, tid = threadIdx.x;
    int r0 = b * STRIP;

    if (tid < STRIP) {
        float D = g_nsmax;
        float nsv = g_ns_sorted[r0 + tid];
        float wp = expf(nsv - D);
        float wn = expf(0.2f * (nsv - D));
        wps[tid] = wp; wns[tid] = wn;
        idx_sm[tid] = g_idx_sorted[r0 + tid];
        g_wpos[r0 + tid] = wp;
        g_wneg[r0 + tid] = wn;
    }
    __syncthreads();

    int d = tid & 127, h = tid >> 7;
    float accp = 0.f, accn = 0.f;
    for (int rr = h * 32; rr < h * 32 + 32; rr++) {
        float n = dn[(size_t)idx_sm[rr] * DIM + d];
        float p = wps[rr] * n, qv = wns[rr] * n;
        g_posw_n[r0 + rr][d] = p;
        g_negw_n[r0 + rr][d] = qv;
        accp += p; accn += qv;
    }
    part[h][0][d] = accp;
    part[h][1][d] = accn;
    __syncthreads();
    if (h == 0) {
        g_stripPos[b][d] = part[0][0][d] + part[1][0][d];
        g_stripNeg[b][d] = part[0][1][d] + part[1][1][d];
    } else if (d < 2) {
        float s = 0.f;
        if (d == 0) { for (int r = 0; r < STRIP; r++) s += wps[r]; g_stripPosW[b] = s; }
        else        { for (int r = 0; r < STRIP; r++) s += wns[r]; g_stripNegW[b] = s; }
    }
}

// ---------------------------------------------------------------------------
// K5: full suffix/prefix tables. Each block redundantly computes its own
// cross-strip offset from the strip sums (smem), then writes its 64 rows.
// Replaces the old single-block stripscan + table pair.
// ---------------------------------------------------------------------------
__global__ __launch_bounds__(288) void table_kernel() {
    __shared__ float sp[NSTRIPS][DIM];     // 16 KB
    __shared__ float sn[NSTRIPS][DIM];     // 16 KB
    __shared__ float spw[NSTRIPS], snw[NSTRIPS];
    int b = blockIdx.x, t = threadIdx.x, r0 = b * STRIP;

    for (int i = t; i < NSTRIPS * DIM; i += 288) {
        ((float*)sp)[i] = ((const float*)g_stripPos)[i];
        ((float*)sn)[i] = ((const float*)g_stripNeg)[i];
    }
    if (t < NSTRIPS) { spw[t] = g_stripPosW[t]; snw[t] = g_stripNegW[t]; }
    __syncthreads();

    if (t < DIM) {
        float acc = 0.f;
        for (int bb = b + 1; bb < NSTRIPS; bb++) acc += sp[bb][t];
        for (int r = STRIP - 1; r >= 0; r--) { acc += g_posw_n[r0 + r][t]; g_S[r0 + r][t] = acc; }
        if (b == 0) g_S[N_NODES][t] = 0.f;
    } else if (t < 2 * DIM) {
        int d = t - DIM;
        float acc = 0.f;
        for (int bb = 0; bb < b; bb++) acc += sn[bb][d];
        for (int r = 0; r < STRIP; r++) { acc += g_negw_n[r0 + r][d]; g_P[r0 + r + 1][d] = acc; }
        if (b == 0) g_P[0][d] = 0.f;
    } else if (t == 2 * DIM) {
        float acc = 0.f;
        for (int bb = b + 1; bb < NSTRIPS; bb++) acc += spw[bb];
        for (int r = STRIP - 1; r >= 0; r--) { acc += g_wpos[r0 + r]; g_wS[r0 + r] = acc; }
        if (b == 0) g_wS[N_NODES] = 0.f;
    } else if (t == 2 * DIM + 1) {
        float acc = 0.f;
        for (int bb = 0; bb < b; bb++) acc += snw[bb];
        for (int r = 0; r < STRIP; r++) { acc += g_wneg[r0 + r]; g_wP[r0 + r + 1] = acc; }
        if (b == 0) g_wP[0] = 0.f;
    }
}

// ---------------------------------------------------------------------------
// K6: output. Per row: binary search crossover c, then
// out = pf + (A*S[c] + B*P[c]) / (A*wS[c] + B*wP[c]).
// A = exp(ps+D-m), B = exp(0.2(ps+D)-m), m = lrelu(ps+D). Both <= 1.
// ---------------------------------------------------------------------------
__global__ __launch_bounds__(256) void out_kernel(const float* __restrict__ pf,
                                                  float* __restrict__ out) {
    __shared__ __align__(16) float ns_sm[N_NODES];
    int tid = threadIdx.x;
    for (int i = tid; i < N_NODES; i += 256) ns_sm[i] = g_ns_sorted[i];
    __syncthreads();

    int row = blockIdx.x * 64 + (tid >> 2);
    int q = tid & 3;
    float ps = g_ps[row];
    float x = ps + g_nsmax;
    float m = fmaxf(x, 0.2f * x);
    float A = expf(x - m);
    float B = expf(0.2f * x - m);

    // c = count of sorted nodes with ns <= -ps  (suffix from c is the positive branch)
    float thr = -ps;
    int lo = 0, hi = N_NODES;
    while (lo < hi) {
        int mid = (lo + hi) >> 1;
        if (ns_sm[mid] <= thr) lo = mid + 1; else hi = mid;
    }
    int c = lo;

    float den = A * g_wS[c] + B * g_wP[c];
    float inv = 1.0f / den;

    const float4* pfp = (const float4*)(pf + (size_t)row * DIM) + q * 8;
    const float4* Sp  = (const float4*)g_S[c] + q * 8;
    const float4* Pp  = (const float4*)g_P[c] + q * 8;
    float4* op = (float4*)(out + (size_t)row * DIM) + q * 8;
    #pragma unroll
    for (int i = 0; i < 8; i++) {
        float4 p = pfp[i], sv = Sp[i], pv = Pp[i];
        float4 o;
        o.x = fmaf(fmaf(A, sv.x, B * pv.x), inv, p.x);
        o.y = fmaf(fmaf(A, sv.y, B * pv.y), inv, p.y);
        o.z = fmaf(fmaf(A, sv.z, B * pv.z), inv, p.z);
        o.w = fmaf(fmaf(A, sv.w, B * pv.w), inv, p.w);
        op[i] = o;
    }
}

// ---------------------------------------------------------------------------
extern "C" void kernel_launch(void* const* d_in, const int* in_sizes, int n_in,
                              void* d_out, int out_size) {
    const float* pf = (const float*)d_in[0];   // patient_features [8192,128]
    const float* dn = (const float*)d_in[1];   // disease_nodes   [2048,128]
    const float* ak = (const float*)d_in[2];   // attn_kernel     [256,1]
    float* out = (float*)d_out;

    score_kernel<<<(B_ROWS + N_NODES) * 4 / 256, 256>>>(pf, dn, ak);
    rank_kernel<<<N_NODES / 128, 256>>>();
    permute_kernel<<<NSTRIPS, 256>>>(dn);
    table_kernel<<<NSTRIPS, 288>>>();
    out_kernel<<<B_ROWS / 64, 256>>>(pf, out);
}